// round 14
// baseline (speedup 1.0000x reference)
#include <cuda_runtime.h>
#include <cuda_fp16.h>
#include <math.h>
#include <stdint.h>

#define B_   2
#define N_   4096
#define E_   1024
#define H_   16
#define HD_  64
#define BH_  32
#define M_   8192
#define MSZ  (M_ * E_)

// ==================== device scratch ====================
__device__ __align__(16) __half g_wh[4][E_ * E_];   // fp16 folded weights
__device__ __align__(16) __half g_xhi[MSZ];         // fp16(x)
__device__ __align__(16) __half g_ahi[MSZ];         // fp16(attn out, summed)
__device__ __align__(16) __half g_qh[MSZ];          // fp16 q (pre-scaled by 0.125*log2e)
__device__ __align__(16) __half g_kh[MSZ];
__device__ __align__(16) __half g_vh[MSZ];
__device__ __align__(16) __half g_attn3[3][MSZ];    // per-level attention outputs (fp16)
__device__ int g_sidx[3][B_][N_];

// ==================== helpers ====================
__device__ __forceinline__ uint32_t smem_u32(const void* p) {
    uint32_t a;
    asm("{ .reg .u64 t; cvta.to.shared.u64 t, %1; cvt.u32.u64 %0, t; }" : "=r"(a) : "l"(p));
    return a;
}
__device__ __forceinline__ void cp16(uint32_t dst, const void* src) {
    asm volatile("cp.async.cg.shared.global [%0], [%1], 16;" :: "r"(dst), "l"(src));
}
#define CP_COMMIT() asm volatile("cp.async.commit_group;" ::: "memory")
#define CP_WAIT(n)  asm volatile("cp.async.wait_group %0;" :: "n"(n) : "memory")

__device__ __forceinline__ void mma16816(float* c, const uint32_t* a, uint32_t b0, uint32_t b1) {
    asm volatile(
        "mma.sync.aligned.m16n8k16.row.col.f32.f16.f16.f32 "
        "{%0,%1,%2,%3}, {%4,%5,%6,%7}, {%8,%9}, {%0,%1,%2,%3};"
        : "+f"(c[0]), "+f"(c[1]), "+f"(c[2]), "+f"(c[3])
        : "r"(a[0]), "r"(a[1]), "r"(a[2]), "r"(a[3]), "r"(b0), "r"(b1));
}
__device__ __forceinline__ void ldsm4(uint32_t addr, uint32_t* r) {
    asm volatile("ldmatrix.sync.aligned.m8n8.x4.shared.b16 {%0,%1,%2,%3}, [%4];"
                 : "=r"(r[0]), "=r"(r[1]), "=r"(r[2]), "=r"(r[3]) : "r"(addr));
}
__device__ __forceinline__ void ldsm4t(uint32_t addr, uint32_t* r) {
    asm volatile("ldmatrix.sync.aligned.m8n8.x4.trans.shared.b16 {%0,%1,%2,%3}, [%4];"
                 : "=r"(r[0]), "=r"(r[1]), "=r"(r[2]), "=r"(r[3]) : "r"(addr));
}
__device__ __forceinline__ uint32_t packh2(float a, float b) {
    __half2 h = __floats2half2_rn(a, b);
    return *(uint32_t*)&h;
}
// raw MUFU exp2 / rcp (no IEEE fixup code — compiler can't emit this without fast-math)
__device__ __forceinline__ float ex2(float x) {
    float y; asm("ex2.approx.f32 %0, %1;" : "=f"(y) : "f"(x)); return y;
}
__device__ __forceinline__ float rcpf(float x) {
    float y; asm("rcp.approx.f32 %0, %1;" : "=f"(y) : "f"(x)); return y;
}

// ==================== fused prep: vectorized LoRA fold (y=0) + x->fp16 (y=1,2) ====================
__global__ void prep_kernel(const float* __restrict__ W0, const float* __restrict__ A0, const float* __restrict__ B0,
                            const float* __restrict__ W1, const float* __restrict__ A1, const float* __restrict__ B1,
                            const float* __restrict__ W2, const float* __restrict__ A2, const float* __restrict__ B2,
                            const float* __restrict__ W3, const float* __restrict__ A3, const float* __restrict__ B3,
                            const float* __restrict__ x) {
    int y = blockIdx.y;
    int linear = blockIdx.x * 256 + threadIdx.x;
    if (y == 0) {
        int which = linear >> 18;              // 262144 float4 per projection
        int i4 = linear & 0x3FFFF;
        const float* W = (which == 0) ? W0 : (which == 1) ? W1 : (which == 2) ? W2 : W3;
        const float* A = (which == 0) ? A0 : (which == 1) ? A1 : (which == 2) ? A2 : A3;
        const float* Bm = (which == 0) ? B0 : (which == 1) ? B1 : (which == 2) ? B2 : B3;
        int idx = i4 * 4;
        int e = idx >> 10;
        int k4 = (idx & 1023) >> 2;
        float4 w = ((const float4*)W)[i4];
        float a0 = w.x, a1 = w.y, a2 = w.z, a3 = w.w;
#pragma unroll
        for (int r = 0; r < 8; r++) {
            float bv = 2.0f * Bm[e * 8 + r];
            float4 av = ((const float4*)A)[r * 256 + k4];
            a0 = fmaf(bv, av.x, a0);
            a1 = fmaf(bv, av.y, a1);
            a2 = fmaf(bv, av.z, a2);
            a3 = fmaf(bv, av.w, a3);
        }
        __half2 h0 = __floats2half2_rn(a0, a1);
        __half2 h1 = __floats2half2_rn(a2, a3);
        uint2 val = { *(uint32_t*)&h0, *(uint32_t*)&h1 };
        *(uint2*)(&g_wh[which][idx]) = val;
    } else {
        int i = linear + (y - 1) * (4096 * 256);
        float4 v = ((const float4*)x)[i];
        __half2* hp = (__half2*)g_xhi + 2 * i;
        hp[0] = __floats2half2_rn(v.x, v.y);
        hp[1] = __floats2half2_rn(v.z, v.w);
    }
}

// ==================== sum 3 fp16 attention levels -> fp16 ====================
__global__ void cvt_sum_kernel() {
    int i = blockIdx.x * 256 + threadIdx.x;
    uint4 a = ((const uint4*)g_attn3[0])[i];
    uint4 b = ((const uint4*)g_attn3[1])[i];
    uint4 c = ((const uint4*)g_attn3[2])[i];
    uint4 r;
    const uint32_t* pa = &a.x;
    const uint32_t* pb = &b.x;
    const uint32_t* pc = &c.x;
    uint32_t* pr = &r.x;
#pragma unroll
    for (int j = 0; j < 4; j++) {
        float2 fa = __half22float2(*(const __half2*)&pa[j]);
        float2 fb = __half22float2(*(const __half2*)&pb[j]);
        float2 fc = __half22float2(*(const __half2*)&pc[j]);
        __half2 h = __floats2half2_rn(fa.x + fb.x + fc.x, fa.y + fb.y + fc.y);
        pr[j] = *(uint32_t*)&h;
    }
    ((uint4*)g_ahi)[i] = r;
}

// ==================== stable counting sort (keys 0..255, N=4096) ====================
static constexpr int SORT_SMEM = 256 * 256 * 2;
__global__ __launch_bounds__(256) void sort_kernel(const int* __restrict__ wb0,
                                                   const int* __restrict__ wb1,
                                                   const int* __restrict__ wb2) {
    extern __shared__ __align__(4) unsigned short cnt[];
    __shared__ unsigned rowsum[256];
    __shared__ unsigned binbase[256];
    int batch = blockIdx.x, level = blockIdx.y;
    const int* wb = (level == 0) ? wb0 : (level == 1) ? wb1 : wb2;
    int t = threadIdx.x;

    unsigned* c32 = (unsigned*)cnt;
#pragma unroll
    for (int i = 0; i < 128; i++) c32[t + 256 * i] = 0;
    __syncthreads();

    int keys[16];
    const int* src = wb + batch * N_ + t * 16;
#pragma unroll
    for (int i = 0; i < 16; i++) {
        int k = src[i];
        keys[i] = k;
        cnt[t * 256 + k]++;
    }
    __syncthreads();

    unsigned run = 0;
    for (int r = 0; r < 256; r++) {
        unsigned v = cnt[r * 256 + t];
        cnt[r * 256 + t] = (unsigned short)run;
        run += v;
    }
    unsigned orig = run;
    rowsum[t] = run;
    __syncthreads();

    for (int ofs = 1; ofs < 256; ofs <<= 1) {
        unsigned yv = (t >= ofs) ? rowsum[t - ofs] : 0;
        __syncthreads();
        rowsum[t] += yv;
        __syncthreads();
    }
    binbase[t] = rowsum[t] - orig;
    __syncthreads();

    int* dst = &g_sidx[level][batch][0];
#pragma unroll
    for (int i = 0; i < 16; i++) {
        int k = keys[i];
        unsigned c0 = cnt[t * 256 + k];
        cnt[t * 256 + k] = (unsigned short)(c0 + 1);
        dst[c0 + binbase[k]] = t * 16 + i;
    }
}

// ==================== HMMA fp16 single-product GEMM: 256 thr, 64x32 warp tiles ====================
static constexpr int TILEB = 128 * 128;
static constexpr int BUFB  = 2 * TILEB;                 // A | B = 32KB
static constexpr int GEMM_SMEM = 2 * BUFB;              // 64KB double-buffered

__global__ __launch_bounds__(256, 2) void gemm_tc(int qkv_mode,
                                                  const float* __restrict__ bias0,
                                                  const float* __restrict__ bias1,
                                                  const float* __restrict__ bias2,
                                                  float* __restrict__ out_ext) {
    extern __shared__ __align__(16) char dsm[];
    int z = blockIdx.z;
    const __half *Ah, *Bh;
    const float* bias;
    if (qkv_mode) {
        Ah = g_xhi; Bh = g_wh[z];
        bias = (z == 0) ? bias0 : (z == 1) ? bias1 : bias2;
    } else {
        Ah = g_ahi; Bh = g_wh[3];
        bias = bias0;
    }

    int tid = threadIdx.x;
    int wid = tid >> 5, lane = tid & 31;
    int g = lane >> 2, t = lane & 3;
    int wm = wid >> 2, wn = wid & 3;                    // 2x4 warp grid, 64x32 tiles
    int m0 = blockIdx.x * 128, n0 = blockIdx.y * 128;

    uint32_t sbase = smem_u32(dsm);
    const __half* srcs[2] = { Ah + (size_t)m0 * E_, Bh + (size_t)n0 * E_ };

    int lc = tid & 7, r5 = (tid >> 3) & 31;
    uint32_t cbyte = (uint32_t)(lc * 16);
    auto load_chunk = [&](int b, int kc) {
#pragma unroll
        for (int tgt = 0; tgt < 2; tgt++) {
            uint32_t tb = sbase + b * BUFB + tgt * TILEB;
            const __half* s = srcs[tgt] + kc * 64 + lc * 8;
#pragma unroll
            for (int p = 0; p < 4; p++) {
                int row = p * 32 + r5;
                cp16(tb + row * 128 + (cbyte ^ ((uint32_t)(row & 7) << 4)),
                     s + (size_t)row * E_);
            }
        }
        CP_COMMIT();
    };

    int lane7 = lane & 7, st = lane >> 3;
    int arow = wm * 64 + (st & 1) * 8 + lane7;          // + mi*16
    uint32_t acolst = (uint32_t)((st >> 1) * 16);
    int brow = wn * 32 + (st >> 1) * 8 + lane7;         // + nb*16
    uint32_t bcolst = (uint32_t)((st & 1) * 16);

    float acc[4][4][4];
#pragma unroll
    for (int i = 0; i < 4; i++)
#pragma unroll
        for (int j = 0; j < 4; j++)
#pragma unroll
            for (int q = 0; q < 4; q++) acc[i][j][q] = 0.f;

    load_chunk(0, 0);

    for (int kc = 0; kc < 16; kc++) {
        int b = kc & 1;
        if (kc + 1 < 16) { load_chunk(b ^ 1, kc + 1); CP_WAIT(1); }
        else             { CP_WAIT(0); }
        __syncthreads();

        uint32_t tA = sbase + b * BUFB;
        uint32_t tB = tA + TILEB;

#pragma unroll
        for (int ks = 0; ks < 4; ks++) {
            uint32_t ko2 = (uint32_t)(ks * 32);
            uint32_t ah[4][4], bh[2][4];
#pragma unroll
            for (int mi = 0; mi < 4; mi++) {
                int row = arow + mi * 16;
                uint32_t off = (uint32_t)(row * 128) + ((ko2 + acolst) ^ ((uint32_t)(row & 7) << 4));
                ldsm4(tA + off, ah[mi]);
            }
#pragma unroll
            for (int nb = 0; nb < 2; nb++) {
                int row = brow + nb * 16;
                uint32_t off = (uint32_t)(row * 128) + ((ko2 + bcolst) ^ ((uint32_t)(row & 7) << 4));
                ldsm4(tB + off, bh[nb]);
            }
#pragma unroll
            for (int mi = 0; mi < 4; mi++)
#pragma unroll
                for (int ni = 0; ni < 4; ni++) {
                    int nb = ni >> 1, hf = (ni & 1) * 2;
                    mma16816(acc[mi][ni], ah[mi], bh[nb][hf], bh[nb][hf + 1]);
                }
        }
        __syncthreads();
    }

    if (qkv_mode) {
        __half* outh = (z == 0) ? g_qh : (z == 1) ? g_kh : g_vh;
        float scl = (z == 0) ? 0.125f * 1.4426950408889634f : 1.0f;
#pragma unroll
        for (int mi = 0; mi < 4; mi++) {
            int r0 = m0 + wm * 64 + mi * 16 + g;
#pragma unroll
            for (int ni = 0; ni < 4; ni++) {
                int col = n0 + wn * 32 + ni * 8 + 2 * t;
                float bx = bias[col], by = bias[col + 1];
                *(__half2*)(outh + (size_t)r0 * E_ + col) =
                    __floats2half2_rn((acc[mi][ni][0] + bx) * scl, (acc[mi][ni][1] + by) * scl);
                *(__half2*)(outh + (size_t)(r0 + 8) * E_ + col) =
                    __floats2half2_rn((acc[mi][ni][2] + bx) * scl, (acc[mi][ni][3] + by) * scl);
            }
        }
    } else {
        float* out = out_ext;
#pragma unroll
        for (int mi = 0; mi < 4; mi++) {
            int r0 = m0 + wm * 64 + mi * 16 + g;
#pragma unroll
            for (int ni = 0; ni < 4; ni++) {
                int col = n0 + wn * 32 + ni * 8 + 2 * t;
                float bx = bias[col], by = bias[col + 1];
                float2 v0 = { acc[mi][ni][0] + bx, acc[mi][ni][1] + by };
                float2 v1 = { acc[mi][ni][2] + bx, acc[mi][ni][3] + by };
                *(float2*)(out + (size_t)r0 * E_ + col) = v0;
                *(float2*)(out + (size_t)(r0 + 8) * E_ + col) = v1;
            }
        }
    }
}

// ==================== fused flash-MMA attention: 128-query blocks, 8 warps ====================
__global__ __launch_bounds__(256) void attn_mma() {
    __shared__ __align__(16) __half sQ[128 * 64];
    __shared__ __align__(16) __half sK[2][64 * 64];
    __shared__ __align__(16) __half sV[2][64 * 64];

    int bh = blockIdx.x;
    int batch = bh >> 4, h = bh & 15;
    int qt = blockIdx.y;
    int level = blockIdx.z;
    const int* sidx = &g_sidx[level][batch][0];
    int tid = threadIdx.x, wid = tid >> 5, lane = tid & 31;
    int g = lane >> 2, t = lane & 3;

    int C = (level == 0) ? 256 : (level == 1) ? 64 : 16;
    int q0 = qt * 128;
    int cg0 = q0 / C, cgL = (q0 + 127) / C;
    int klo = cg0 ? (cg0 - 1) * C : 0;
    int khi = (cgL + 1) * C;
    int ntiles = (khi - klo + 63) >> 6;
    int cg = (q0 + wid * 16) / C;
    int wlo = cg ? (cg - 1) * C : 0;
    int whi = (cg + 1) * C;

    int fc = tid & 7, fr = tid >> 3;
    uint32_t fcb = (uint32_t)(fc * 16);
    size_t hbase = (size_t)(batch * N_) * E_ + h * HD_;
    uint32_t sq = smem_u32(sQ);
    uint32_t skb[2] = { smem_u32(sK[0]), smem_u32(sK[1]) };
    uint32_t svb[2] = { smem_u32(sV[0]), smem_u32(sV[1]) };

    auto load_kv = [&](int buf, int tile) {
#pragma unroll
        for (int p = 0; p < 2; p++) {
            int row = p * 32 + fr;
            int pos = klo + tile * 64 + row;
            int tok = sidx[min(pos, N_ - 1)];
            uint32_t off = (uint32_t)(row * 128) + (fcb ^ ((uint32_t)(row & 7) << 4));
            cp16(skb[buf] + off, (const uint4*)(g_kh + hbase + (size_t)tok * E_) + fc);
            cp16(svb[buf] + off, (const uint4*)(g_vh + hbase + (size_t)tok * E_) + fc);
        }
        CP_COMMIT();
    };

#pragma unroll
    for (int p = 0; p < 4; p++) {
        int row = p * 32 + fr;
        int tok = sidx[q0 + row];
        uint32_t off = (uint32_t)(row * 128) + (fcb ^ ((uint32_t)(row & 7) << 4));
        cp16(sq + off, (const uint4*)(g_qh + hbase + (size_t)tok * E_) + fc);
    }
    load_kv(0, 0);

    int lane7 = lane & 7, st = lane >> 3;
    int kbrow = (st >> 1) * 8 + lane7;
    uint32_t kbcol = (uint32_t)((st & 1) * 16);
    int vrow = (st & 1) * 8 + lane7;
    uint32_t vcol = (uint32_t)((lane >> 4) * 16);

    uint32_t aq[4][4];
    float o[8][4];
#pragma unroll
    for (int i = 0; i < 8; i++)
#pragma unroll
        for (int j = 0; j < 4; j++) o[i][j] = 0.f;
    float m0 = -1e30f, m1 = -1e30f, l0 = 0.f, l1 = 0.f;

    for (int tile = 0; tile < ntiles; tile++) {
        int buf = tile & 1;
        CP_WAIT(0);
        __syncthreads();
        if (tile == 0) {
            int arow = wid * 16 + (st & 1) * 8 + lane7;
            uint32_t acol = (uint32_t)((st >> 1) * 16);
#pragma unroll
            for (int kk = 0; kk < 4; kk++) {
                uint32_t off = (uint32_t)(arow * 128) + ((acol + kk * 32) ^ ((uint32_t)(arow & 7) << 4));
                ldsm4(sq + off, aq[kk]);
            }
        }
        if (tile + 1 < ntiles) load_kv(buf ^ 1, tile + 1);

        int tlo = klo + tile * 64;
        bool active = (wlo < tlo + 64) && (whi > tlo);
        bool partial = (wlo > tlo) || (whi < tlo + 64);
        if (active) {
            uint32_t sk = skb[buf], sv = svb[buf];
            float c[8][4];
#pragma unroll
            for (int i = 0; i < 8; i++)
#pragma unroll
                for (int j = 0; j < 4; j++) c[i][j] = 0.f;
#pragma unroll
            for (int kk = 0; kk < 4; kk++) {
                uint32_t ko2 = (uint32_t)(kk * 32);
#pragma unroll
                for (int nt = 0; nt < 4; nt++) {
                    int row = nt * 16 + kbrow;
                    uint32_t off = (uint32_t)(row * 128) + ((ko2 + kbcol) ^ ((uint32_t)(row & 7) << 4));
                    uint32_t bf[4];
                    ldsm4(sk + off, bf);
                    mma16816(c[2 * nt],     aq[kk], bf[0], bf[1]);
                    mma16816(c[2 * nt + 1], aq[kk], bf[2], bf[3]);
                }
            }
            if (partial) {
#pragma unroll
                for (int nt = 0; nt < 8; nt++) {
                    int col0 = tlo + nt * 8 + 2 * t;
                    if (col0 < wlo || col0 >= whi)         { c[nt][0] = -1e30f; c[nt][2] = -1e30f; }
                    if (col0 + 1 < wlo || col0 + 1 >= whi) { c[nt][1] = -1e30f; c[nt][3] = -1e30f; }
                }
            }
            float mx0 = -1e30f, mx1 = -1e30f;
#pragma unroll
            for (int nt = 0; nt < 8; nt++) {
                mx0 = fmaxf(mx0, fmaxf(c[nt][0], c[nt][1]));
                mx1 = fmaxf(mx1, fmaxf(c[nt][2], c[nt][3]));
            }
            mx0 = fmaxf(mx0, __shfl_xor_sync(0xFFFFFFFFu, mx0, 1));
            mx0 = fmaxf(mx0, __shfl_xor_sync(0xFFFFFFFFu, mx0, 2));
            mx1 = fmaxf(mx1, __shfl_xor_sync(0xFFFFFFFFu, mx1, 1));
            mx1 = fmaxf(mx1, __shfl_xor_sync(0xFFFFFFFFu, mx1, 2));
            float mn0 = fmaxf(m0, mx0), mn1 = fmaxf(m1, mx1);
            float cr0 = ex2(m0 - mn0), cr1 = ex2(m1 - mn1);
            m0 = mn0; m1 = mn1;
            l0 *= cr0; l1 *= cr1;
            uint32_t pA[8], pB[8];
#pragma unroll
            for (int nt = 0; nt < 8; nt++) {
                float e0 = ex2(c[nt][0] - m0), e1 = ex2(c[nt][1] - m0);
                float e2 = ex2(c[nt][2] - m1), e3 = ex2(c[nt][3] - m1);
                l0 += e0 + e1; l1 += e2 + e3;
                pA[nt] = packh2(e0, e1);
                pB[nt] = packh2(e2, e3);
            }
#pragma unroll
            for (int ht = 0; ht < 8; ht++) {
                o[ht][0] *= cr0; o[ht][1] *= cr0;
                o[ht][2] *= cr1; o[ht][3] *= cr1;
            }
#pragma unroll
            for (int kj = 0; kj < 4; kj++) {
                uint32_t a[4] = { pA[2 * kj], pB[2 * kj], pA[2 * kj + 1], pB[2 * kj + 1] };
#pragma unroll
                for (int ht = 0; ht < 4; ht++) {
                    int row = kj * 16 + vrow;
                    uint32_t off = (uint32_t)(row * 128) +
                                   (((uint32_t)(ht * 32) + vcol) ^ ((uint32_t)(row & 7) << 4));
                    uint32_t b[4];
                    ldsm4t(sv + off, b);
                    mma16816(o[2 * ht],     a, b[0], b[1]);
                    mma16816(o[2 * ht + 1], a, b[2], b[3]);
                }
            }
        }
        __syncthreads();
    }

    l0 += __shfl_xor_sync(0xFFFFFFFFu, l0, 1);
    l0 += __shfl_xor_sync(0xFFFFFFFFu, l0, 2);
    l1 += __shfl_xor_sync(0xFFFFFFFFu, l1, 1);
    l1 += __shfl_xor_sync(0xFFFFFFFFu, l1, 2);
    float inv0 = rcpf(3.f * l0);
    float inv1 = rcpf(3.f * l1);

    int pq0 = q0 + wid * 16 + g;
    int tok0 = sidx[pq0];
    int tok1 = sidx[pq0 + 8];
    __half* base = g_attn3[level];
    __half* d0 = base + (size_t)(batch * N_ + tok0) * E_ + h * HD_;
    __half* d1 = base + (size_t)(batch * N_ + tok1) * E_ + h * HD_;
#pragma unroll
    for (int nt = 0; nt < 8; nt++) {
        int col = nt * 8 + 2 * t;
        *(__half2*)(d0 + col) = __floats2half2_rn(o[nt][0] * inv0, o[nt][1] * inv0);
        *(__half2*)(d1 + col) = __floats2half2_rn(o[nt][2] * inv1, o[nt][3] * inv1);
    }
}

// ==================== launch ====================
extern "C" void kernel_launch(void* const* d_in, const int* in_sizes, int n_in,
                              void* d_out, int out_size) {
    (void)in_sizes; (void)n_in; (void)out_size;
    const float* x   = (const float*)d_in[0];
    const int*   wbc = (const int*)d_in[1];
    const int*   wbm = (const int*)d_in[2];
    const int*   wbf = (const int*)d_in[3];
    const float* Wp[4] = { (const float*)d_in[4],  (const float*)d_in[8],
                           (const float*)d_in[12], (const float*)d_in[16] };
    const float* bp[4] = { (const float*)d_in[5],  (const float*)d_in[9],
                           (const float*)d_in[13], (const float*)d_in[17] };
    const float* Ap[4] = { (const float*)d_in[6],  (const float*)d_in[10],
                           (const float*)d_in[14], (const float*)d_in[18] };
    const float* Lp[4] = { (const float*)d_in[7],  (const float*)d_in[11],
                           (const float*)d_in[15], (const float*)d_in[19] };
    float* out = (float*)d_out;

    cudaFuncSetAttribute(gemm_tc, cudaFuncAttributeMaxDynamicSharedMemorySize, GEMM_SMEM);
    cudaFuncSetAttribute(sort_kernel, cudaFuncAttributeMaxDynamicSharedMemorySize, SORT_SMEM);

    // 1) fused LoRA fold (vectorized, fp16) + x->fp16
    prep_kernel<<<dim3(4096, 3), 256>>>(
        Wp[0], Ap[0], Lp[0], Wp[1], Ap[1], Lp[1],
        Wp[2], Ap[2], Lp[2], Wp[3], Ap[3], Lp[3], x);

    // 2) fused q,k,v projections (single-product fp16)
    gemm_tc<<<dim3(M_ / 128, E_ / 128, 3), 256, GEMM_SMEM>>>(1, bp[0], bp[1], bp[2], nullptr);

    // 3) stable counting sort per (batch, level)
    sort_kernel<<<dim3(B_, 3), 256, SORT_SMEM>>>(wbc, wbm, wbf);

    // 4) fused three-level flash-MMA attention (raw ex2.approx softmax)
    attn_mma<<<dim3(BH_, N_ / 128, 3), 256>>>();

    // 5) sum levels (fp16 in) -> fp16
    cvt_sum_kernel<<<(MSZ / 8) / 256, 256>>>();

    // 6) output projection
    gemm_tc<<<dim3(M_ / 128, E_ / 128, 1), 256, GEMM_SMEM>>>(0, bp[3], nullptr, nullptr, out);
}

// round 15
// speedup vs baseline: 1.5023x; 1.5023x over previous
#include <cuda_runtime.h>
#include <cuda_fp16.h>
#include <math.h>
#include <stdint.h>

#define B_   2
#define N_   4096
#define E_   1024
#define H_   16
#define HD_  64
#define BH_  32
#define M_   8192
#define MSZ  (M_ * E_)

// ==================== device scratch ====================
__device__ __align__(16) __half g_wh[4][E_ * E_];   // fp16 folded weights
__device__ __align__(16) __half g_xhi[MSZ];         // fp16(x)
__device__ __align__(16) __half g_ahi[MSZ];         // fp16(attn out, summed)
__device__ __align__(16) __half g_qh[MSZ];          // fp16 q (pre-scaled by 0.125*log2e)
__device__ __align__(16) __half g_kh[MSZ];
__device__ __align__(16) __half g_vh[MSZ];
__device__ __align__(16) __half g_attn3[3][MSZ];    // per-level attention outputs (fp16)
__device__ int g_sidx[3][B_][N_];

// ==================== helpers ====================
__device__ __forceinline__ uint32_t smem_u32(const void* p) {
    uint32_t a;
    asm("{ .reg .u64 t; cvta.to.shared.u64 t, %1; cvt.u32.u64 %0, t; }" : "=r"(a) : "l"(p));
    return a;
}
__device__ __forceinline__ void cp16(uint32_t dst, const void* src) {
    asm volatile("cp.async.cg.shared.global [%0], [%1], 16;" :: "r"(dst), "l"(src));
}
#define CP_COMMIT() asm volatile("cp.async.commit_group;" ::: "memory")
#define CP_WAIT(n)  asm volatile("cp.async.wait_group %0;" :: "n"(n) : "memory")

__device__ __forceinline__ void mma16816(float* c, const uint32_t* a, uint32_t b0, uint32_t b1) {
    asm volatile(
        "mma.sync.aligned.m16n8k16.row.col.f32.f16.f16.f32 "
        "{%0,%1,%2,%3}, {%4,%5,%6,%7}, {%8,%9}, {%0,%1,%2,%3};"
        : "+f"(c[0]), "+f"(c[1]), "+f"(c[2]), "+f"(c[3])
        : "r"(a[0]), "r"(a[1]), "r"(a[2]), "r"(a[3]), "r"(b0), "r"(b1));
}
__device__ __forceinline__ void ldsm4(uint32_t addr, uint32_t* r) {
    asm volatile("ldmatrix.sync.aligned.m8n8.x4.shared.b16 {%0,%1,%2,%3}, [%4];"
                 : "=r"(r[0]), "=r"(r[1]), "=r"(r[2]), "=r"(r[3]) : "r"(addr));
}
__device__ __forceinline__ void ldsm4t(uint32_t addr, uint32_t* r) {
    asm volatile("ldmatrix.sync.aligned.m8n8.x4.trans.shared.b16 {%0,%1,%2,%3}, [%4];"
                 : "=r"(r[0]), "=r"(r[1]), "=r"(r[2]), "=r"(r[3]) : "r"(addr));
}
__device__ __forceinline__ uint32_t packh2(float a, float b) {
    __half2 h = __floats2half2_rn(a, b);
    return *(uint32_t*)&h;
}

// ==================== fused prep: vectorized LoRA fold (y=0) + x->fp16 (y=1,2) ====================
__global__ void prep_kernel(const float* __restrict__ W0, const float* __restrict__ A0, const float* __restrict__ B0,
                            const float* __restrict__ W1, const float* __restrict__ A1, const float* __restrict__ B1,
                            const float* __restrict__ W2, const float* __restrict__ A2, const float* __restrict__ B2,
                            const float* __restrict__ W3, const float* __restrict__ A3, const float* __restrict__ B3,
                            const float* __restrict__ x) {
    int y = blockIdx.y;
    int linear = blockIdx.x * 256 + threadIdx.x;
    if (y == 0) {
        int which = linear >> 18;              // 262144 float4 per projection
        int i4 = linear & 0x3FFFF;
        const float* W = (which == 0) ? W0 : (which == 1) ? W1 : (which == 2) ? W2 : W3;
        const float* A = (which == 0) ? A0 : (which == 1) ? A1 : (which == 2) ? A2 : A3;
        const float* Bm = (which == 0) ? B0 : (which == 1) ? B1 : (which == 2) ? B2 : B3;
        int idx = i4 * 4;
        int e = idx >> 10;
        int k4 = (idx & 1023) >> 2;
        float4 w = ((const float4*)W)[i4];
        float a0 = w.x, a1 = w.y, a2 = w.z, a3 = w.w;
#pragma unroll
        for (int r = 0; r < 8; r++) {
            float bv = 2.0f * Bm[e * 8 + r];
            float4 av = ((const float4*)A)[r * 256 + k4];
            a0 = fmaf(bv, av.x, a0);
            a1 = fmaf(bv, av.y, a1);
            a2 = fmaf(bv, av.z, a2);
            a3 = fmaf(bv, av.w, a3);
        }
        __half2 h0 = __floats2half2_rn(a0, a1);
        __half2 h1 = __floats2half2_rn(a2, a3);
        uint2 val = { *(uint32_t*)&h0, *(uint32_t*)&h1 };
        *(uint2*)(&g_wh[which][idx]) = val;
    } else {
        int i = linear + (y - 1) * (4096 * 256);
        float4 v = ((const float4*)x)[i];
        __half2* hp = (__half2*)g_xhi + 2 * i;
        hp[0] = __floats2half2_rn(v.x, v.y);
        hp[1] = __floats2half2_rn(v.z, v.w);
    }
}

// ==================== sum 3 fp16 attention levels -> fp16 (hadd2) ====================
__global__ void cvt_sum_kernel() {
    int i = blockIdx.x * 256 + threadIdx.x;
    uint4 a = ((const uint4*)g_attn3[0])[i];
    uint4 b = ((const uint4*)g_attn3[1])[i];
    uint4 c = ((const uint4*)g_attn3[2])[i];
    uint4 r;
    const uint32_t* pa = &a.x;
    const uint32_t* pb = &b.x;
    const uint32_t* pc = &c.x;
    uint32_t* pr = &r.x;
#pragma unroll
    for (int j = 0; j < 4; j++) {
        __half2 h = __hadd2(__hadd2(*(const __half2*)&pa[j], *(const __half2*)&pb[j]),
                            *(const __half2*)&pc[j]);
        pr[j] = *(uint32_t*)&h;
    }
    ((uint4*)g_ahi)[i] = r;
}

// ==================== stable counting sort (keys 0..255, N=4096) ====================
static constexpr int SORT_SMEM = 256 * 256 * 2;
__global__ __launch_bounds__(256) void sort_kernel(const int* __restrict__ wb0,
                                                   const int* __restrict__ wb1,
                                                   const int* __restrict__ wb2) {
    extern __shared__ __align__(4) unsigned short cnt[];
    __shared__ unsigned rowsum[256];
    __shared__ unsigned binbase[256];
    int batch = blockIdx.x, level = blockIdx.y;
    const int* wb = (level == 0) ? wb0 : (level == 1) ? wb1 : wb2;
    int t = threadIdx.x;

    unsigned* c32 = (unsigned*)cnt;
#pragma unroll
    for (int i = 0; i < 128; i++) c32[t + 256 * i] = 0;
    __syncthreads();

    int keys[16];
    const int* src = wb + batch * N_ + t * 16;
#pragma unroll
    for (int i = 0; i < 16; i++) {
        int k = src[i];
        keys[i] = k;
        cnt[t * 256 + k]++;
    }
    __syncthreads();

    unsigned run = 0;
    for (int r = 0; r < 256; r++) {
        unsigned v = cnt[r * 256 + t];
        cnt[r * 256 + t] = (unsigned short)run;
        run += v;
    }
    unsigned orig = run;
    rowsum[t] = run;
    __syncthreads();

    for (int ofs = 1; ofs < 256; ofs <<= 1) {
        unsigned yv = (t >= ofs) ? rowsum[t - ofs] : 0;
        __syncthreads();
        rowsum[t] += yv;
        __syncthreads();
    }
    binbase[t] = rowsum[t] - orig;
    __syncthreads();

    int* dst = &g_sidx[level][batch][0];
#pragma unroll
    for (int i = 0; i < 16; i++) {
        int k = keys[i];
        unsigned c0 = cnt[t * 256 + k];
        cnt[t * 256 + k] = (unsigned short)(c0 + 1);
        dst[c0 + binbase[k]] = t * 16 + i;
    }
}

// ==================== HMMA fp16 single-product GEMM: 256 thr, 64x32 warp tiles ====================
static constexpr int TILEB = 128 * 128;
static constexpr int BUFB  = 2 * TILEB;                 // A | B = 32KB
static constexpr int GEMM_SMEM = 2 * BUFB;              // 64KB double-buffered

__global__ __launch_bounds__(256, 2) void gemm_tc(int qkv_mode,
                                                  const float* __restrict__ bias0,
                                                  const float* __restrict__ bias1,
                                                  const float* __restrict__ bias2,
                                                  float* __restrict__ out_ext) {
    extern __shared__ __align__(16) char dsm[];
    int z = blockIdx.z;
    const __half *Ah, *Bh;
    const float* bias;
    if (qkv_mode) {
        Ah = g_xhi; Bh = g_wh[z];
        bias = (z == 0) ? bias0 : (z == 1) ? bias1 : bias2;
    } else {
        Ah = g_ahi; Bh = g_wh[3];
        bias = bias0;
    }

    int tid = threadIdx.x;
    int wid = tid >> 5, lane = tid & 31;
    int g = lane >> 2, t = lane & 3;
    int wm = wid >> 2, wn = wid & 3;                    // 2x4 warp grid, 64x32 tiles
    int m0 = blockIdx.x * 128, n0 = blockIdx.y * 128;

    uint32_t sbase = smem_u32(dsm);
    const __half* srcs[2] = { Ah + (size_t)m0 * E_, Bh + (size_t)n0 * E_ };

    int lc = tid & 7, r5 = (tid >> 3) & 31;
    uint32_t cbyte = (uint32_t)(lc * 16);
    auto load_chunk = [&](int b, int kc) {
#pragma unroll
        for (int tgt = 0; tgt < 2; tgt++) {
            uint32_t tb = sbase + b * BUFB + tgt * TILEB;
            const __half* s = srcs[tgt] + kc * 64 + lc * 8;
#pragma unroll
            for (int p = 0; p < 4; p++) {
                int row = p * 32 + r5;
                cp16(tb + row * 128 + (cbyte ^ ((uint32_t)(row & 7) << 4)),
                     s + (size_t)row * E_);
            }
        }
        CP_COMMIT();
    };

    int lane7 = lane & 7, st = lane >> 3;
    int arow = wm * 64 + (st & 1) * 8 + lane7;          // + mi*16
    uint32_t acolst = (uint32_t)((st >> 1) * 16);
    int brow = wn * 32 + (st >> 1) * 8 + lane7;         // + nb*16
    uint32_t bcolst = (uint32_t)((st & 1) * 16);

    float acc[4][4][4];
#pragma unroll
    for (int i = 0; i < 4; i++)
#pragma unroll
        for (int j = 0; j < 4; j++)
#pragma unroll
            for (int q = 0; q < 4; q++) acc[i][j][q] = 0.f;

    load_chunk(0, 0);

    for (int kc = 0; kc < 16; kc++) {
        int b = kc & 1;
        if (kc + 1 < 16) { load_chunk(b ^ 1, kc + 1); CP_WAIT(1); }
        else             { CP_WAIT(0); }
        __syncthreads();

        uint32_t tA = sbase + b * BUFB;
        uint32_t tB = tA + TILEB;

#pragma unroll
        for (int ks = 0; ks < 4; ks++) {
            uint32_t ko2 = (uint32_t)(ks * 32);
            uint32_t ah[4][4], bh[2][4];
#pragma unroll
            for (int mi = 0; mi < 4; mi++) {
                int row = arow + mi * 16;
                uint32_t off = (uint32_t)(row * 128) + ((ko2 + acolst) ^ ((uint32_t)(row & 7) << 4));
                ldsm4(tA + off, ah[mi]);
            }
#pragma unroll
            for (int nb = 0; nb < 2; nb++) {
                int row = brow + nb * 16;
                uint32_t off = (uint32_t)(row * 128) + ((ko2 + bcolst) ^ ((uint32_t)(row & 7) << 4));
                ldsm4(tB + off, bh[nb]);
            }
#pragma unroll
            for (int mi = 0; mi < 4; mi++)
#pragma unroll
                for (int ni = 0; ni < 4; ni++) {
                    int nb = ni >> 1, hf = (ni & 1) * 2;
                    mma16816(acc[mi][ni], ah[mi], bh[nb][hf], bh[nb][hf + 1]);
                }
        }
        __syncthreads();
    }

    if (qkv_mode) {
        __half* outh = (z == 0) ? g_qh : (z == 1) ? g_kh : g_vh;
        float scl = (z == 0) ? 0.125f * 1.4426950408889634f : 1.0f;
#pragma unroll
        for (int mi = 0; mi < 4; mi++) {
            int r0 = m0 + wm * 64 + mi * 16 + g;
#pragma unroll
            for (int ni = 0; ni < 4; ni++) {
                int col = n0 + wn * 32 + ni * 8 + 2 * t;
                float bx = bias[col], by = bias[col + 1];
                *(__half2*)(outh + (size_t)r0 * E_ + col) =
                    __floats2half2_rn((acc[mi][ni][0] + bx) * scl, (acc[mi][ni][1] + by) * scl);
                *(__half2*)(outh + (size_t)(r0 + 8) * E_ + col) =
                    __floats2half2_rn((acc[mi][ni][2] + bx) * scl, (acc[mi][ni][3] + by) * scl);
            }
        }
    } else {
        float* out = out_ext;
#pragma unroll
        for (int mi = 0; mi < 4; mi++) {
            int r0 = m0 + wm * 64 + mi * 16 + g;
#pragma unroll
            for (int ni = 0; ni < 4; ni++) {
                int col = n0 + wn * 32 + ni * 8 + 2 * t;
                float bx = bias[col], by = bias[col + 1];
                float2 v0 = { acc[mi][ni][0] + bx, acc[mi][ni][1] + by };
                float2 v1 = { acc[mi][ni][2] + bx, acc[mi][ni][3] + by };
                *(float2*)(out + (size_t)r0 * E_ + col) = v0;
                *(float2*)(out + (size_t)(r0 + 8) * E_ + col) = v1;
            }
        }
    }
}

// ==================== fused flash-MMA attention: 128-query blocks, 8 warps ====================
__global__ __launch_bounds__(256) void attn_mma() {
    __shared__ __align__(16) __half sQ[128 * 64];
    __shared__ __align__(16) __half sK[2][64 * 64];
    __shared__ __align__(16) __half sV[2][64 * 64];

    int bh = blockIdx.x;
    int batch = bh >> 4, h = bh & 15;
    int qt = blockIdx.y;
    int level = blockIdx.z;
    const int* sidx = &g_sidx[level][batch][0];
    int tid = threadIdx.x, wid = tid >> 5, lane = tid & 31;
    int g = lane >> 2, t = lane & 3;

    int C = (level == 0) ? 256 : (level == 1) ? 64 : 16;
    int q0 = qt * 128;
    int cg0 = q0 / C, cgL = (q0 + 127) / C;
    int klo = cg0 ? (cg0 - 1) * C : 0;
    int khi = (cgL + 1) * C;
    int ntiles = (khi - klo + 63) >> 6;
    int cg = (q0 + wid * 16) / C;
    int wlo = cg ? (cg - 1) * C : 0;
    int whi = (cg + 1) * C;

    int fc = tid & 7, fr = tid >> 3;
    uint32_t fcb = (uint32_t)(fc * 16);
    size_t hbase = (size_t)(batch * N_) * E_ + h * HD_;
    uint32_t sq = smem_u32(sQ);
    uint32_t skb[2] = { smem_u32(sK[0]), smem_u32(sK[1]) };
    uint32_t svb[2] = { smem_u32(sV[0]), smem_u32(sV[1]) };

    auto load_kv = [&](int buf, int tile) {
#pragma unroll
        for (int p = 0; p < 2; p++) {
            int row = p * 32 + fr;
            int pos = klo + tile * 64 + row;
            int tok = sidx[min(pos, N_ - 1)];
            uint32_t off = (uint32_t)(row * 128) + (fcb ^ ((uint32_t)(row & 7) << 4));
            cp16(skb[buf] + off, (const uint4*)(g_kh + hbase + (size_t)tok * E_) + fc);
            cp16(svb[buf] + off, (const uint4*)(g_vh + hbase + (size_t)tok * E_) + fc);
        }
        CP_COMMIT();
    };

#pragma unroll
    for (int p = 0; p < 4; p++) {
        int row = p * 32 + fr;
        int tok = sidx[q0 + row];
        uint32_t off = (uint32_t)(row * 128) + (fcb ^ ((uint32_t)(row & 7) << 4));
        cp16(sq + off, (const uint4*)(g_qh + hbase + (size_t)tok * E_) + fc);
    }
    load_kv(0, 0);

    int lane7 = lane & 7, st = lane >> 3;
    int kbrow = (st >> 1) * 8 + lane7;
    uint32_t kbcol = (uint32_t)((st & 1) * 16);
    int vrow = (st & 1) * 8 + lane7;
    uint32_t vcol = (uint32_t)((lane >> 4) * 16);

    uint32_t aq[4][4];
    float o[8][4];
#pragma unroll
    for (int i = 0; i < 8; i++)
#pragma unroll
        for (int j = 0; j < 4; j++) o[i][j] = 0.f;
    float m0 = -1e30f, m1 = -1e30f, l0 = 0.f, l1 = 0.f;

    for (int tile = 0; tile < ntiles; tile++) {
        int buf = tile & 1;
        CP_WAIT(0);
        __syncthreads();
        if (tile == 0) {
            int arow = wid * 16 + (st & 1) * 8 + lane7;
            uint32_t acol = (uint32_t)((st >> 1) * 16);
#pragma unroll
            for (int kk = 0; kk < 4; kk++) {
                uint32_t off = (uint32_t)(arow * 128) + ((acol + kk * 32) ^ ((uint32_t)(arow & 7) << 4));
                ldsm4(sq + off, aq[kk]);
            }
        }
        if (tile + 1 < ntiles) load_kv(buf ^ 1, tile + 1);

        int tlo = klo + tile * 64;
        bool active = (wlo < tlo + 64) && (whi > tlo);
        bool partial = (wlo > tlo) || (whi < tlo + 64);
        if (active) {
            uint32_t sk = skb[buf], sv = svb[buf];
            float c[8][4];
#pragma unroll
            for (int i = 0; i < 8; i++)
#pragma unroll
                for (int j = 0; j < 4; j++) c[i][j] = 0.f;
#pragma unroll
            for (int kk = 0; kk < 4; kk++) {
                uint32_t ko2 = (uint32_t)(kk * 32);
#pragma unroll
                for (int nt = 0; nt < 4; nt++) {
                    int row = nt * 16 + kbrow;
                    uint32_t off = (uint32_t)(row * 128) + ((ko2 + kbcol) ^ ((uint32_t)(row & 7) << 4));
                    uint32_t bf[4];
                    ldsm4(sk + off, bf);
                    mma16816(c[2 * nt],     aq[kk], bf[0], bf[1]);
                    mma16816(c[2 * nt + 1], aq[kk], bf[2], bf[3]);
                }
            }
            if (partial) {
#pragma unroll
                for (int nt = 0; nt < 8; nt++) {
                    int col0 = tlo + nt * 8 + 2 * t;
                    if (col0 < wlo || col0 >= whi)         { c[nt][0] = -1e30f; c[nt][2] = -1e30f; }
                    if (col0 + 1 < wlo || col0 + 1 >= whi) { c[nt][1] = -1e30f; c[nt][3] = -1e30f; }
                }
            }
            float mx0 = -1e30f, mx1 = -1e30f;
#pragma unroll
            for (int nt = 0; nt < 8; nt++) {
                mx0 = fmaxf(mx0, fmaxf(c[nt][0], c[nt][1]));
                mx1 = fmaxf(mx1, fmaxf(c[nt][2], c[nt][3]));
            }
            mx0 = fmaxf(mx0, __shfl_xor_sync(0xFFFFFFFFu, mx0, 1));
            mx0 = fmaxf(mx0, __shfl_xor_sync(0xFFFFFFFFu, mx0, 2));
            mx1 = fmaxf(mx1, __shfl_xor_sync(0xFFFFFFFFu, mx1, 1));
            mx1 = fmaxf(mx1, __shfl_xor_sync(0xFFFFFFFFu, mx1, 2));
            float mn0 = fmaxf(m0, mx0), mn1 = fmaxf(m1, mx1);
            float cr0 = exp2f(m0 - mn0), cr1 = exp2f(m1 - mn1);
            m0 = mn0; m1 = mn1;
            l0 *= cr0; l1 *= cr1;
            uint32_t pA[8], pB[8];
#pragma unroll
            for (int nt = 0; nt < 8; nt++) {
                float e0 = exp2f(c[nt][0] - m0), e1 = exp2f(c[nt][1] - m0);
                float e2 = exp2f(c[nt][2] - m1), e3 = exp2f(c[nt][3] - m1);
                l0 += e0 + e1; l1 += e2 + e3;
                pA[nt] = packh2(e0, e1);
                pB[nt] = packh2(e2, e3);
            }
#pragma unroll
            for (int ht = 0; ht < 8; ht++) {
                o[ht][0] *= cr0; o[ht][1] *= cr0;
                o[ht][2] *= cr1; o[ht][3] *= cr1;
            }
#pragma unroll
            for (int kj = 0; kj < 4; kj++) {
                uint32_t a[4] = { pA[2 * kj], pB[2 * kj], pA[2 * kj + 1], pB[2 * kj + 1] };
#pragma unroll
                for (int ht = 0; ht < 4; ht++) {
                    int row = kj * 16 + vrow;
                    uint32_t off = (uint32_t)(row * 128) +
                                   (((uint32_t)(ht * 32) + vcol) ^ ((uint32_t)(row & 7) << 4));
                    uint32_t b[4];
                    ldsm4t(sv + off, b);
                    mma16816(o[2 * ht],     a, b[0], b[1]);
                    mma16816(o[2 * ht + 1], a, b[2], b[3]);
                }
            }
        }
        __syncthreads();
    }

    l0 += __shfl_xor_sync(0xFFFFFFFFu, l0, 1);
    l0 += __shfl_xor_sync(0xFFFFFFFFu, l0, 2);
    l1 += __shfl_xor_sync(0xFFFFFFFFu, l1, 1);
    l1 += __shfl_xor_sync(0xFFFFFFFFu, l1, 2);
    float inv0 = 1.f / (3.f * l0);
    float inv1 = 1.f / (3.f * l1);

    int pq0 = q0 + wid * 16 + g;
    int tok0 = sidx[pq0];
    int tok1 = sidx[pq0 + 8];
    __half* base = g_attn3[level];
    __half* d0 = base + (size_t)(batch * N_ + tok0) * E_ + h * HD_;
    __half* d1 = base + (size_t)(batch * N_ + tok1) * E_ + h * HD_;
#pragma unroll
    for (int nt = 0; nt < 8; nt++) {
        int col = nt * 8 + 2 * t;
        *(__half2*)(d0 + col) = __floats2half2_rn(o[nt][0] * inv0, o[nt][1] * inv0);
        *(__half2*)(d1 + col) = __floats2half2_rn(o[nt][2] * inv1, o[nt][3] * inv1);
    }
}

// ==================== launch ====================
extern "C" void kernel_launch(void* const* d_in, const int* in_sizes, int n_in,
                              void* d_out, int out_size) {
    (void)in_sizes; (void)n_in; (void)out_size;
    const float* x   = (const float*)d_in[0];
    const int*   wbc = (const int*)d_in[1];
    const int*   wbm = (const int*)d_in[2];
    const int*   wbf = (const int*)d_in[3];
    const float* Wp[4] = { (const float*)d_in[4],  (const float*)d_in[8],
                           (const float*)d_in[12], (const float*)d_in[16] };
    const float* bp[4] = { (const float*)d_in[5],  (const float*)d_in[9],
                           (const float*)d_in[13], (const float*)d_in[17] };
    const float* Ap[4] = { (const float*)d_in[6],  (const float*)d_in[10],
                           (const float*)d_in[14], (const float*)d_in[18] };
    const float* Lp[4] = { (const float*)d_in[7],  (const float*)d_in[11],
                           (const float*)d_in[15], (const float*)d_in[19] };
    float* out = (float*)d_out;

    cudaFuncSetAttribute(gemm_tc, cudaFuncAttributeMaxDynamicSharedMemorySize, GEMM_SMEM);
    cudaFuncSetAttribute(sort_kernel, cudaFuncAttributeMaxDynamicSharedMemorySize, SORT_SMEM);

    // 1) fused LoRA fold (vectorized, fp16) + x->fp16
    prep_kernel<<<dim3(4096, 3), 256>>>(
        Wp[0], Ap[0], Lp[0], Wp[1], Ap[1], Lp[1],
        Wp[2], Ap[2], Lp[2], Wp[3], Ap[3], Lp[3], x);

    // 2) fused q,k,v projections (single-product fp16)
    gemm_tc<<<dim3(M_ / 128, E_ / 128, 3), 256, GEMM_SMEM>>>(1, bp[0], bp[1], bp[2], nullptr);

    // 3) stable counting sort per (batch, level)
    sort_kernel<<<dim3(B_, 3), 256, SORT_SMEM>>>(wbc, wbm, wbf);

    // 4) fused three-level flash-MMA attention (exp2f softmax, proven)
    attn_mma<<<dim3(BH_, N_ / 128, 3), 256>>>();

    // 5) sum levels (fp16 hadd2) -> fp16
    cvt_sum_kernel<<<(MSZ / 8) / 256, 256>>>();

    // 6) output projection
    gemm_tc<<<dim3(M_ / 128, E_ / 128, 1), 256, GEMM_SMEM>>>(0, bp[3], nullptr, nullptr, out);
}

// round 16
// speedup vs baseline: 1.5221x; 1.0132x over previous
#include <cuda_runtime.h>
#include <cuda_fp16.h>
#include <math.h>
#include <stdint.h>

#define B_   2
#define N_   4096
#define E_   1024
#define H_   16
#define HD_  64
#define BH_  32
#define M_   8192
#define MSZ  (M_ * E_)

// ==================== device scratch ====================
__device__ __align__(16) __half g_wh[4][E_ * E_];   // fp16 folded weights
__device__ __align__(16) __half g_xhi[MSZ];         // fp16(x)
__device__ __align__(16) __half g_ahi[MSZ];         // fp16(attn out, summed)
__device__ __align__(16) __half g_qh[MSZ];          // fp16 q (pre-scaled by 0.125*log2e)
__device__ __align__(16) __half g_kh[MSZ];
__device__ __align__(16) __half g_vh[MSZ];
__device__ __align__(16) __half g_attn3[3][MSZ];    // per-level attention outputs (fp16)
__device__ int g_sidx[3][B_][N_];

// ==================== helpers ====================
__device__ __forceinline__ uint32_t smem_u32(const void* p) {
    uint32_t a;
    asm("{ .reg .u64 t; cvta.to.shared.u64 t, %1; cvt.u32.u64 %0, t; }" : "=r"(a) : "l"(p));
    return a;
}
__device__ __forceinline__ void cp16(uint32_t dst, const void* src) {
    asm volatile("cp.async.cg.shared.global [%0], [%1], 16;" :: "r"(dst), "l"(src));
}
#define CP_COMMIT() asm volatile("cp.async.commit_group;" ::: "memory")
#define CP_WAIT(n)  asm volatile("cp.async.wait_group %0;" :: "n"(n) : "memory")

__device__ __forceinline__ void mma16816(float* c, const uint32_t* a, uint32_t b0, uint32_t b1) {
    asm volatile(
        "mma.sync.aligned.m16n8k16.row.col.f32.f16.f16.f32 "
        "{%0,%1,%2,%3}, {%4,%5,%6,%7}, {%8,%9}, {%0,%1,%2,%3};"
        : "+f"(c[0]), "+f"(c[1]), "+f"(c[2]), "+f"(c[3])
        : "r"(a[0]), "r"(a[1]), "r"(a[2]), "r"(a[3]), "r"(b0), "r"(b1));
}
__device__ __forceinline__ void ldsm4(uint32_t addr, uint32_t* r) {
    asm volatile("ldmatrix.sync.aligned.m8n8.x4.shared.b16 {%0,%1,%2,%3}, [%4];"
                 : "=r"(r[0]), "=r"(r[1]), "=r"(r[2]), "=r"(r[3]) : "r"(addr));
}
__device__ __forceinline__ void ldsm4t(uint32_t addr, uint32_t* r) {
    asm volatile("ldmatrix.sync.aligned.m8n8.x4.trans.shared.b16 {%0,%1,%2,%3}, [%4];"
                 : "=r"(r[0]), "=r"(r[1]), "=r"(r[2]), "=r"(r[3]) : "r"(addr));
}
// packed half2 exp2 via MUFU f16x2 path: 1 MUFU per 2 exps
__device__ __forceinline__ uint32_t ex2h2(float a, float b) {
    __half2 h = __floats2half2_rn(a, b);
    uint32_t hi = *(uint32_t*)&h;
    uint32_t r;
    asm("ex2.approx.f16x2 %0, %1;" : "=r"(r) : "r"(hi));
    return r;
}

// ==================== fused prep: vectorized LoRA fold (y=0) + x->fp16 (y=1,2) ====================
__global__ void prep_kernel(const float* __restrict__ W0, const float* __restrict__ A0, const float* __restrict__ B0,
                            const float* __restrict__ W1, const float* __restrict__ A1, const float* __restrict__ B1,
                            const float* __restrict__ W2, const float* __restrict__ A2, const float* __restrict__ B2,
                            const float* __restrict__ W3, const float* __restrict__ A3, const float* __restrict__ B3,
                            const float* __restrict__ x) {
    int y = blockIdx.y;
    int linear = blockIdx.x * 256 + threadIdx.x;
    if (y == 0) {
        int which = linear >> 18;              // 262144 float4 per projection
        int i4 = linear & 0x3FFFF;
        const float* W = (which == 0) ? W0 : (which == 1) ? W1 : (which == 2) ? W2 : W3;
        const float* A = (which == 0) ? A0 : (which == 1) ? A1 : (which == 2) ? A2 : A3;
        const float* Bm = (which == 0) ? B0 : (which == 1) ? B1 : (which == 2) ? B2 : B3;
        int idx = i4 * 4;
        int e = idx >> 10;
        int k4 = (idx & 1023) >> 2;
        float4 w = ((const float4*)W)[i4];
        float a0 = w.x, a1 = w.y, a2 = w.z, a3 = w.w;
#pragma unroll
        for (int r = 0; r < 8; r++) {
            float bv = 2.0f * Bm[e * 8 + r];
            float4 av = ((const float4*)A)[r * 256 + k4];
            a0 = fmaf(bv, av.x, a0);
            a1 = fmaf(bv, av.y, a1);
            a2 = fmaf(bv, av.z, a2);
            a3 = fmaf(bv, av.w, a3);
        }
        __half2 h0 = __floats2half2_rn(a0, a1);
        __half2 h1 = __floats2half2_rn(a2, a3);
        uint2 val = { *(uint32_t*)&h0, *(uint32_t*)&h1 };
        *(uint2*)(&g_wh[which][idx]) = val;
    } else {
        int i = linear + (y - 1) * (4096 * 256);
        float4 v = ((const float4*)x)[i];
        __half2* hp = (__half2*)g_xhi + 2 * i;
        hp[0] = __floats2half2_rn(v.x, v.y);
        hp[1] = __floats2half2_rn(v.z, v.w);
    }
}

// ==================== sum 3 fp16 attention levels -> fp16 (hadd2) ====================
__global__ void cvt_sum_kernel() {
    int i = blockIdx.x * 256 + threadIdx.x;
    uint4 a = ((const uint4*)g_attn3[0])[i];
    uint4 b = ((const uint4*)g_attn3[1])[i];
    uint4 c = ((const uint4*)g_attn3[2])[i];
    uint4 r;
    const uint32_t* pa = &a.x;
    const uint32_t* pb = &b.x;
    const uint32_t* pc = &c.x;
    uint32_t* pr = &r.x;
#pragma unroll
    for (int j = 0; j < 4; j++) {
        __half2 h = __hadd2(__hadd2(*(const __half2*)&pa[j], *(const __half2*)&pb[j]),
                            *(const __half2*)&pc[j]);
        pr[j] = *(uint32_t*)&h;
    }
    ((uint4*)g_ahi)[i] = r;
}

// ==================== stable counting sort (keys 0..255, N=4096) ====================
static constexpr int SORT_SMEM = 256 * 256 * 2;
__global__ __launch_bounds__(256) void sort_kernel(const int* __restrict__ wb0,
                                                   const int* __restrict__ wb1,
                                                   const int* __restrict__ wb2) {
    extern __shared__ __align__(4) unsigned short cnt[];
    __shared__ unsigned rowsum[256];
    __shared__ unsigned binbase[256];
    int batch = blockIdx.x, level = blockIdx.y;
    const int* wb = (level == 0) ? wb0 : (level == 1) ? wb1 : wb2;
    int t = threadIdx.x;

    unsigned* c32 = (unsigned*)cnt;
#pragma unroll
    for (int i = 0; i < 128; i++) c32[t + 256 * i] = 0;
    __syncthreads();

    int keys[16];
    const int* src = wb + batch * N_ + t * 16;
#pragma unroll
    for (int i = 0; i < 16; i++) {
        int k = src[i];
        keys[i] = k;
        cnt[t * 256 + k]++;
    }
    __syncthreads();

    unsigned run = 0;
    for (int r = 0; r < 256; r++) {
        unsigned v = cnt[r * 256 + t];
        cnt[r * 256 + t] = (unsigned short)run;
        run += v;
    }
    unsigned orig = run;
    rowsum[t] = run;
    __syncthreads();

    for (int ofs = 1; ofs < 256; ofs <<= 1) {
        unsigned yv = (t >= ofs) ? rowsum[t - ofs] : 0;
        __syncthreads();
        rowsum[t] += yv;
        __syncthreads();
    }
    binbase[t] = rowsum[t] - orig;
    __syncthreads();

    int* dst = &g_sidx[level][batch][0];
#pragma unroll
    for (int i = 0; i < 16; i++) {
        int k = keys[i];
        unsigned c0 = cnt[t * 256 + k];
        cnt[t * 256 + k] = (unsigned short)(c0 + 1);
        dst[c0 + binbase[k]] = t * 16 + i;
    }
}

// ==================== HMMA fp16 single-product GEMM: 256 thr, 64x32 warp tiles ====================
static constexpr int TILEB = 128 * 128;
static constexpr int BUFB  = 2 * TILEB;                 // A | B = 32KB
static constexpr int GEMM_SMEM = 2 * BUFB;              // 64KB double-buffered

__global__ __launch_bounds__(256, 2) void gemm_tc(int qkv_mode,
                                                  const float* __restrict__ bias0,
                                                  const float* __restrict__ bias1,
                                                  const float* __restrict__ bias2,
                                                  float* __restrict__ out_ext) {
    extern __shared__ __align__(16) char dsm[];
    int z = blockIdx.z;
    const __half *Ah, *Bh;
    const float* bias;
    if (qkv_mode) {
        Ah = g_xhi; Bh = g_wh[z];
        bias = (z == 0) ? bias0 : (z == 1) ? bias1 : bias2;
    } else {
        Ah = g_ahi; Bh = g_wh[3];
        bias = bias0;
    }

    int tid = threadIdx.x;
    int wid = tid >> 5, lane = tid & 31;
    int g = lane >> 2, t = lane & 3;
    int wm = wid >> 2, wn = wid & 3;                    // 2x4 warp grid, 64x32 tiles
    int m0 = blockIdx.x * 128, n0 = blockIdx.y * 128;

    uint32_t sbase = smem_u32(dsm);
    const __half* srcs[2] = { Ah + (size_t)m0 * E_, Bh + (size_t)n0 * E_ };

    int lc = tid & 7, r5 = (tid >> 3) & 31;
    uint32_t cbyte = (uint32_t)(lc * 16);
    auto load_chunk = [&](int b, int kc) {
#pragma unroll
        for (int tgt = 0; tgt < 2; tgt++) {
            uint32_t tb = sbase + b * BUFB + tgt * TILEB;
            const __half* s = srcs[tgt] + kc * 64 + lc * 8;
#pragma unroll
            for (int p = 0; p < 4; p++) {
                int row = p * 32 + r5;
                cp16(tb + row * 128 + (cbyte ^ ((uint32_t)(row & 7) << 4)),
                     s + (size_t)row * E_);
            }
        }
        CP_COMMIT();
    };

    int lane7 = lane & 7, st = lane >> 3;
    int arow = wm * 64 + (st & 1) * 8 + lane7;          // + mi*16
    uint32_t acolst = (uint32_t)((st >> 1) * 16);
    int brow = wn * 32 + (st >> 1) * 8 + lane7;         // + nb*16
    uint32_t bcolst = (uint32_t)((st & 1) * 16);

    float acc[4][4][4];
#pragma unroll
    for (int i = 0; i < 4; i++)
#pragma unroll
        for (int j = 0; j < 4; j++)
#pragma unroll
            for (int q = 0; q < 4; q++) acc[i][j][q] = 0.f;

    load_chunk(0, 0);

    for (int kc = 0; kc < 16; kc++) {
        int b = kc & 1;
        if (kc + 1 < 16) { load_chunk(b ^ 1, kc + 1); CP_WAIT(1); }
        else             { CP_WAIT(0); }
        __syncthreads();

        uint32_t tA = sbase + b * BUFB;
        uint32_t tB = tA + TILEB;

#pragma unroll
        for (int ks = 0; ks < 4; ks++) {
            uint32_t ko2 = (uint32_t)(ks * 32);
            uint32_t ah[4][4], bh[2][4];
#pragma unroll
            for (int mi = 0; mi < 4; mi++) {
                int row = arow + mi * 16;
                uint32_t off = (uint32_t)(row * 128) + ((ko2 + acolst) ^ ((uint32_t)(row & 7) << 4));
                ldsm4(tA + off, ah[mi]);
            }
#pragma unroll
            for (int nb = 0; nb < 2; nb++) {
                int row = brow + nb * 16;
                uint32_t off = (uint32_t)(row * 128) + ((ko2 + bcolst) ^ ((uint32_t)(row & 7) << 4));
                ldsm4(tB + off, bh[nb]);
            }
#pragma unroll
            for (int mi = 0; mi < 4; mi++)
#pragma unroll
                for (int ni = 0; ni < 4; ni++) {
                    int nb = ni >> 1, hf = (ni & 1) * 2;
                    mma16816(acc[mi][ni], ah[mi], bh[nb][hf], bh[nb][hf + 1]);
                }
        }
        __syncthreads();
    }

    if (qkv_mode) {
        __half* outh = (z == 0) ? g_qh : (z == 1) ? g_kh : g_vh;
        float scl = (z == 0) ? 0.125f * 1.4426950408889634f : 1.0f;
#pragma unroll
        for (int mi = 0; mi < 4; mi++) {
            int r0 = m0 + wm * 64 + mi * 16 + g;
#pragma unroll
            for (int ni = 0; ni < 4; ni++) {
                int col = n0 + wn * 32 + ni * 8 + 2 * t;
                float bx = bias[col], by = bias[col + 1];
                *(__half2*)(outh + (size_t)r0 * E_ + col) =
                    __floats2half2_rn((acc[mi][ni][0] + bx) * scl, (acc[mi][ni][1] + by) * scl);
                *(__half2*)(outh + (size_t)(r0 + 8) * E_ + col) =
                    __floats2half2_rn((acc[mi][ni][2] + bx) * scl, (acc[mi][ni][3] + by) * scl);
            }
        }
    } else {
        float* out = out_ext;
#pragma unroll
        for (int mi = 0; mi < 4; mi++) {
            int r0 = m0 + wm * 64 + mi * 16 + g;
#pragma unroll
            for (int ni = 0; ni < 4; ni++) {
                int col = n0 + wn * 32 + ni * 8 + 2 * t;
                float bx = bias[col], by = bias[col + 1];
                float2 v0 = { acc[mi][ni][0] + bx, acc[mi][ni][1] + by };
                float2 v1 = { acc[mi][ni][2] + bx, acc[mi][ni][3] + by };
                *(float2*)(out + (size_t)r0 * E_ + col) = v0;
                *(float2*)(out + (size_t)(r0 + 8) * E_ + col) = v1;
            }
        }
    }
}

// ==================== fused flash-MMA attention: 128-query blocks, 8 warps ====================
__global__ __launch_bounds__(256) void attn_mma() {
    __shared__ __align__(16) __half sQ[128 * 64];
    __shared__ __align__(16) __half sK[2][64 * 64];
    __shared__ __align__(16) __half sV[2][64 * 64];

    int bh = blockIdx.x;
    int batch = bh >> 4, h = bh & 15;
    int qt = blockIdx.y;
    int level = blockIdx.z;
    const int* sidx = &g_sidx[level][batch][0];
    int tid = threadIdx.x, wid = tid >> 5, lane = tid & 31;
    int g = lane >> 2, t = lane & 3;

    int C = (level == 0) ? 256 : (level == 1) ? 64 : 16;
    int q0 = qt * 128;
    int cg0 = q0 / C, cgL = (q0 + 127) / C;
    int klo = cg0 ? (cg0 - 1) * C : 0;
    int khi = (cgL + 1) * C;
    int ntiles = (khi - klo + 63) >> 6;
    int cg = (q0 + wid * 16) / C;
    int wlo = cg ? (cg - 1) * C : 0;
    int whi = (cg + 1) * C;

    int fc = tid & 7, fr = tid >> 3;
    uint32_t fcb = (uint32_t)(fc * 16);
    size_t hbase = (size_t)(batch * N_) * E_ + h * HD_;
    uint32_t sq = smem_u32(sQ);
    uint32_t skb[2] = { smem_u32(sK[0]), smem_u32(sK[1]) };
    uint32_t svb[2] = { smem_u32(sV[0]), smem_u32(sV[1]) };

    auto load_kv = [&](int buf, int tile) {
#pragma unroll
        for (int p = 0; p < 2; p++) {
            int row = p * 32 + fr;
            int pos = klo + tile * 64 + row;
            int tok = sidx[min(pos, N_ - 1)];
            uint32_t off = (uint32_t)(row * 128) + (fcb ^ ((uint32_t)(row & 7) << 4));
            cp16(skb[buf] + off, (const uint4*)(g_kh + hbase + (size_t)tok * E_) + fc);
            cp16(svb[buf] + off, (const uint4*)(g_vh + hbase + (size_t)tok * E_) + fc);
        }
        CP_COMMIT();
    };

#pragma unroll
    for (int p = 0; p < 4; p++) {
        int row = p * 32 + fr;
        int tok = sidx[q0 + row];
        uint32_t off = (uint32_t)(row * 128) + (fcb ^ ((uint32_t)(row & 7) << 4));
        cp16(sq + off, (const uint4*)(g_qh + hbase + (size_t)tok * E_) + fc);
    }
    load_kv(0, 0);

    int lane7 = lane & 7, st = lane >> 3;
    int kbrow = (st >> 1) * 8 + lane7;
    uint32_t kbcol = (uint32_t)((st & 1) * 16);
    int vrow = (st & 1) * 8 + lane7;
    uint32_t vcol = (uint32_t)((lane >> 4) * 16);

    uint32_t aq[4][4];
    float o[8][4];
#pragma unroll
    for (int i = 0; i < 8; i++)
#pragma unroll
        for (int j = 0; j < 4; j++) o[i][j] = 0.f;
    float m0 = -1e30f, m1 = -1e30f, l0 = 0.f, l1 = 0.f;

    for (int tile = 0; tile < ntiles; tile++) {
        int buf = tile & 1;
        CP_WAIT(0);
        __syncthreads();
        if (tile == 0) {
            int arow = wid * 16 + (st & 1) * 8 + lane7;
            uint32_t acol = (uint32_t)((st >> 1) * 16);
#pragma unroll
            for (int kk = 0; kk < 4; kk++) {
                uint32_t off = (uint32_t)(arow * 128) + ((acol + kk * 32) ^ ((uint32_t)(arow & 7) << 4));
                ldsm4(sq + off, aq[kk]);
            }
        }
        if (tile + 1 < ntiles) load_kv(buf ^ 1, tile + 1);

        int tlo = klo + tile * 64;
        bool active = (wlo < tlo + 64) && (whi > tlo);
        bool partial = (wlo > tlo) || (whi < tlo + 64);
        if (active) {
            uint32_t sk = skb[buf], sv = svb[buf];
            float c[8][4];
#pragma unroll
            for (int i = 0; i < 8; i++)
#pragma unroll
                for (int j = 0; j < 4; j++) c[i][j] = 0.f;
#pragma unroll
            for (int kk = 0; kk < 4; kk++) {
                uint32_t ko2 = (uint32_t)(kk * 32);
#pragma unroll
                for (int nt = 0; nt < 4; nt++) {
                    int row = nt * 16 + kbrow;
                    uint32_t off = (uint32_t)(row * 128) + ((ko2 + kbcol) ^ ((uint32_t)(row & 7) << 4));
                    uint32_t bf[4];
                    ldsm4(sk + off, bf);
                    mma16816(c[2 * nt],     aq[kk], bf[0], bf[1]);
                    mma16816(c[2 * nt + 1], aq[kk], bf[2], bf[3]);
                }
            }
            if (partial) {
#pragma unroll
                for (int nt = 0; nt < 8; nt++) {
                    int col0 = tlo + nt * 8 + 2 * t;
                    if (col0 < wlo || col0 >= whi)         { c[nt][0] = -1e30f; c[nt][2] = -1e30f; }
                    if (col0 + 1 < wlo || col0 + 1 >= whi) { c[nt][1] = -1e30f; c[nt][3] = -1e30f; }
                }
            }
            float mx0 = -1e30f, mx1 = -1e30f;
#pragma unroll
            for (int nt = 0; nt < 8; nt++) {
                mx0 = fmaxf(mx0, fmaxf(c[nt][0], c[nt][1]));
                mx1 = fmaxf(mx1, fmaxf(c[nt][2], c[nt][3]));
            }
            mx0 = fmaxf(mx0, __shfl_xor_sync(0xFFFFFFFFu, mx0, 1));
            mx0 = fmaxf(mx0, __shfl_xor_sync(0xFFFFFFFFu, mx0, 2));
            mx1 = fmaxf(mx1, __shfl_xor_sync(0xFFFFFFFFu, mx1, 1));
            mx1 = fmaxf(mx1, __shfl_xor_sync(0xFFFFFFFFu, mx1, 2));
            float mn0 = fmaxf(m0, mx0), mn1 = fmaxf(m1, mx1);
            float cr0 = exp2f(m0 - mn0), cr1 = exp2f(m1 - mn1);
            m0 = mn0; m1 = mn1;
            l0 *= cr0; l1 *= cr1;
            uint32_t pA[8], pB[8];
#pragma unroll
            for (int nt = 0; nt < 8; nt++) {
                pA[nt] = ex2h2(c[nt][0] - m0, c[nt][1] - m0);
                pB[nt] = ex2h2(c[nt][2] - m1, c[nt][3] - m1);
                float2 fa = __half22float2(*(const __half2*)&pA[nt]);
                float2 fb = __half22float2(*(const __half2*)&pB[nt]);
                l0 += fa.x + fa.y;
                l1 += fb.x + fb.y;
            }
#pragma unroll
            for (int ht = 0; ht < 8; ht++) {
                o[ht][0] *= cr0; o[ht][1] *= cr0;
                o[ht][2] *= cr1; o[ht][3] *= cr1;
            }
#pragma unroll
            for (int kj = 0; kj < 4; kj++) {
                uint32_t a[4] = { pA[2 * kj], pB[2 * kj], pA[2 * kj + 1], pB[2 * kj + 1] };
#pragma unroll
                for (int ht = 0; ht < 4; ht++) {
                    int row = kj * 16 + vrow;
                    uint32_t off = (uint32_t)(row * 128) +
                                   (((uint32_t)(ht * 32) + vcol) ^ ((uint32_t)(row & 7) << 4));
                    uint32_t b[4];
                    ldsm4t(sv + off, b);
                    mma16816(o[2 * ht],     a, b[0], b[1]);
                    mma16816(o[2 * ht + 1], a, b[2], b[3]);
                }
            }
        }
        __syncthreads();
    }

    l0 += __shfl_xor_sync(0xFFFFFFFFu, l0, 1);
    l0 += __shfl_xor_sync(0xFFFFFFFFu, l0, 2);
    l1 += __shfl_xor_sync(0xFFFFFFFFu, l1, 1);
    l1 += __shfl_xor_sync(0xFFFFFFFFu, l1, 2);
    float inv0 = 1.f / (3.f * l0);
    float inv1 = 1.f / (3.f * l1);

    int pq0 = q0 + wid * 16 + g;
    int tok0 = sidx[pq0];
    int tok1 = sidx[pq0 + 8];
    __half* base = g_attn3[level];
    __half* d0 = base + (size_t)(batch * N_ + tok0) * E_ + h * HD_;
    __half* d1 = base + (size_t)(batch * N_ + tok1) * E_ + h * HD_;
#pragma unroll
    for (int nt = 0; nt < 8; nt++) {
        int col = nt * 8 + 2 * t;
        *(__half2*)(d0 + col) = __floats2half2_rn(o[nt][0] * inv0, o[nt][1] * inv0);
        *(__half2*)(d1 + col) = __floats2half2_rn(o[nt][2] * inv1, o[nt][3] * inv1);
    }
}

// ==================== launch ====================
extern "C" void kernel_launch(void* const* d_in, const int* in_sizes, int n_in,
                              void* d_out, int out_size) {
    (void)in_sizes; (void)n_in; (void)out_size;
    const float* x   = (const float*)d_in[0];
    const int*   wbc = (const int*)d_in[1];
    const int*   wbm = (const int*)d_in[2];
    const int*   wbf = (const int*)d_in[3];
    const float* Wp[4] = { (const float*)d_in[4],  (const float*)d_in[8],
                           (const float*)d_in[12], (const float*)d_in[16] };
    const float* bp[4] = { (const float*)d_in[5],  (const float*)d_in[9],
                           (const float*)d_in[13], (const float*)d_in[17] };
    const float* Ap[4] = { (const float*)d_in[6],  (const float*)d_in[10],
                           (const float*)d_in[14], (const float*)d_in[18] };
    const float* Lp[4] = { (const float*)d_in[7],  (const float*)d_in[11],
                           (const float*)d_in[15], (const float*)d_in[19] };
    float* out = (float*)d_out;

    cudaFuncSetAttribute(gemm_tc, cudaFuncAttributeMaxDynamicSharedMemorySize, GEMM_SMEM);
    cudaFuncSetAttribute(sort_kernel, cudaFuncAttributeMaxDynamicSharedMemorySize, SORT_SMEM);

    // 1) fused LoRA fold (vectorized, fp16) + x->fp16
    prep_kernel<<<dim3(4096, 3), 256>>>(
        Wp[0], Ap[0], Lp[0], Wp[1], Ap[1], Lp[1],
        Wp[2], Ap[2], Lp[2], Wp[3], Ap[3], Lp[3], x);

    // 2) fused q,k,v projections (single-product fp16)
    gemm_tc<<<dim3(M_ / 128, E_ / 128, 3), 256, GEMM_SMEM>>>(1, bp[0], bp[1], bp[2], nullptr);

    // 3) stable counting sort per (batch, level)
    sort_kernel<<<dim3(B_, 3), 256, SORT_SMEM>>>(wbc, wbm, wbf);

    // 4) fused three-level flash-MMA attention (f16x2 MUFU softmax)
    attn_mma<<<dim3(BH_, N_ / 128, 3), 256>>>();

    // 5) sum levels (fp16 hadd2) -> fp16
    cvt_sum_kernel<<<(MSZ / 8) / 256, 256>>>();

    // 6) output projection
    gemm_tc<<<dim3(M_ / 128, E_ / 128, 1), 256, GEMM_SMEM>>>(0, bp[3], nullptr, nullptr, out);
}